// round 8
// baseline (speedup 1.0000x reference)
#include <cuda_runtime.h>
#include <cuda_bf16.h>
#include <math.h>
#include <stdint.h>

// Problem constants: N=64, T=512, D=512, H=512, fp32
#define NB   64
#define TT   512
#define DD   512
#define HH   512
#define MM   (NB * TT)

// ---------------------------------------------------------------------------
// f32x2 packed-math helpers
// ---------------------------------------------------------------------------
__device__ __forceinline__ void ffma2(unsigned long long& acc,
                                      unsigned long long a,
                                      unsigned long long b) {
    asm("fma.rn.f32x2 %0, %1, %2, %0;" : "+l"(acc) : "l"(a), "l"(b));
}
__device__ __forceinline__ unsigned long long add2(unsigned long long a,
                                                   unsigned long long b) {
    unsigned long long r;
    asm("add.rn.f32x2 %0, %1, %2;" : "=l"(r) : "l"(a), "l"(b));
    return r;
}
__device__ __forceinline__ unsigned long long pack_dup(float v) {
    unsigned long long r;
    unsigned u = __float_as_uint(v);
    asm("mov.b64 %0, {%1, %1};" : "=l"(r) : "r"(u));
    return r;
}

// mbarrier helpers -----------------------------------------------------------
#define MBAR_INIT(addr, cnt) \
    asm volatile("mbarrier.init.shared.b64 [%0], %1;" :: "r"(addr), "r"(cnt) : "memory")
#define MBAR_EXPECT_TX(addr, bytes) \
    asm volatile("mbarrier.arrive.expect_tx.shared.b64 _, [%0], %1;" \
                 :: "r"(addr), "r"(bytes) : "memory")
#define MBAR_ARRIVE_REMOTE(addr) \
    asm volatile("mbarrier.arrive.shared::cluster.b64 _, [%0];" :: "r"(addr) : "memory")

__device__ __forceinline__ void mbar_wait_parity(uint32_t mbar, uint32_t parity) {
    asm volatile(
        "{\n\t"
        ".reg .pred P;\n\t"
        "WL_%=:\n\t"
        "mbarrier.try_wait.parity.acquire.cluster.shared::cta.b64 P, [%0], %1, 0x989680;\n\t"
        "@P bra WD_%=;\n\t"
        "bra WL_%=;\n\t"
        "WD_%=:\n\t"
        "}" :: "r"(mbar), "r"(parity) : "memory");
}

__device__ __forceinline__ void st_async_b64(uint32_t raddr, unsigned long long v,
                                             uint32_t rmbar) {
    asm volatile(
        "st.async.shared::cluster.mbarrier::complete_tx::bytes.b64 [%0], %1, [%2];"
        :: "r"(raddr), "l"(v), "r"(rmbar) : "memory");
}

// ---------------------------------------------------------------------------
// Kernel A: xwx = x @ Wx + b  (into d_out), FFMA2 SGEMM (unchanged)
// ---------------------------------------------------------------------------
#define BM 128
#define BN 128
#define BK 8

__global__ __launch_bounds__(256) void gemm_xwx_kernel(
    const float* __restrict__ X,
    const float* __restrict__ Wx,
    const float* __restrict__ bias,
    float* __restrict__ out)
{
    __shared__ float2 Asd[BK][BM];
    __shared__ float  Bs[BK][BN];

    const int tid = threadIdx.x;
    const int m0 = blockIdx.y * BM;
    const int n0 = blockIdx.x * BN;

    const int arow = tid >> 1;
    const int acol = (tid & 1) * 4;
    const int brow = tid >> 5;
    const int bcol = (tid & 31) * 4;

    const int ty = tid >> 4;
    const int tx = tid & 15;

    unsigned long long acc2[8][4];
#pragma unroll
    for (int i = 0; i < 8; ++i)
#pragma unroll
        for (int j = 0; j < 4; ++j) acc2[i][j] = 0ULL;

    for (int k0 = 0; k0 < DD; k0 += BK) {
        float4 av = *reinterpret_cast<const float4*>(
            X + (size_t)(m0 + arow) * DD + k0 + acol);
        float4 bv = *reinterpret_cast<const float4*>(
            Wx + (size_t)(k0 + brow) * HH + n0 + bcol);

        Asd[acol + 0][arow] = make_float2(av.x, av.x);
        Asd[acol + 1][arow] = make_float2(av.y, av.y);
        Asd[acol + 2][arow] = make_float2(av.z, av.z);
        Asd[acol + 3][arow] = make_float2(av.w, av.w);
        *reinterpret_cast<float4*>(&Bs[brow][bcol]) = bv;
        __syncthreads();

#pragma unroll
        for (int k = 0; k < BK; ++k) {
            unsigned long long a2[8], b2[4];
            ulonglong2 t0 = *reinterpret_cast<const ulonglong2*>(&Bs[k][tx * 8]);
            ulonglong2 t1 = *reinterpret_cast<const ulonglong2*>(&Bs[k][tx * 8 + 4]);
            b2[0] = t0.x; b2[1] = t0.y; b2[2] = t1.x; b2[3] = t1.y;
#pragma unroll
            for (int i = 0; i < 8; ++i)
                a2[i] = *reinterpret_cast<const unsigned long long*>(&Asd[k][ty * 8 + i]);
#pragma unroll
            for (int i = 0; i < 8; ++i)
#pragma unroll
                for (int j = 0; j < 4; ++j)
                    ffma2(acc2[i][j], a2[i], b2[j]);
        }
        __syncthreads();
    }

    unsigned long long bb2[4];
    {
        ulonglong2 t0 = *reinterpret_cast<const ulonglong2*>(bias + n0 + tx * 8);
        ulonglong2 t1 = *reinterpret_cast<const ulonglong2*>(bias + n0 + tx * 8 + 4);
        bb2[0] = t0.x; bb2[1] = t0.y; bb2[2] = t1.x; bb2[3] = t1.y;
    }
#pragma unroll
    for (int i = 0; i < 8; ++i) {
        float* orow = out + (size_t)(m0 + ty * 8 + i) * HH + n0 + tx * 8;
        ulonglong2 v0, v1;
        v0.x = add2(acc2[i][0], bb2[0]);
        v0.y = add2(acc2[i][1], bb2[1]);
        v1.x = add2(acc2[i][2], bb2[2]);
        v1.y = add2(acc2[i][3], bb2[3]);
        *reinterpret_cast<ulonglong2*>(orow)     = v0;
        *reinterpret_cast<ulonglong2*>(orow + 4) = v1;
    }
}

// ---------------------------------------------------------------------------
// Kernel B: cluster recurrence.
//   NEW vs R6:
//   (1) h exchange buffer stores DUPLICATED {h,h} b64 values -> consumers
//       ld.shared.b64 straight into FFMA2; all pack MOVs removed.
//   (2) per-source-rank full barriers (8 per buffer): warp tid>>6 == r waits
//       only for chunk r (k in [64r,64r+64)) produced by CTA r. Exchange
//       latency/skew overlaps with compute of already-arrived chunks.
// ---------------------------------------------------------------------------
#define CLUSTER       8
#define NCTA          128
#define BATCH_PER_CL  4
#define COLS_PER_CTA  64

// smem layout (bytes):
//   [0, 32768)       hdup: [2 buf][4 batch][512 k] x b64 {h,h}
//   [32768, 65536)   red:  [32][4][64] floats
//   [65536, ...)     mbarriers: full[2][8] (stride 8B), then empty[2]
#define HDUP_BYTES   32768
#define RED_OFF_F    8192                    // float index of red
#define MBAR_OFF     65536
#define MB_FULL(p, r) (MBAR_OFF + ((p) * 8 + (r)) * 8)
#define MB_EMPTY(p)   (MBAR_OFF + 128 + (p) * 8)
#define RNN_SMEM_BYTES (MBAR_OFF + 160)

#define CHUNK_TX_BYTES (BATCH_PER_CL * COLS_PER_CTA * 8)   // 2048 per chunk fill

__global__ __launch_bounds__(512, 1) __cluster_dims__(CLUSTER, 1, 1)
void rnn_cluster_kernel(const float* __restrict__ h0,
                        const float* __restrict__ Wh,
                        float* __restrict__ out)
{
    extern __shared__ float smem[];
    unsigned long long* hdup = reinterpret_cast<unsigned long long*>(smem);
    float* red = smem + RED_OFF_F;

    const int tid = threadIdx.x;
    uint32_t rank;
    asm("mov.u32 %0, %%cluster_ctarank;" : "=r"(rank));
    const int cid = blockIdx.x >> 3;
    const int b0  = cid * BATCH_PER_CL;

    const int kq    = tid >> 4;          // 0..31 (half-warp k-group)
    const int cq    = tid & 15;          // 0..15
    const int kbase = kq * 16;
    const int chunk = tid >> 6;          // 0..7: which source rank my warp consumes
    const int jg0   = (int)rank * COLS_PER_CTA + cq * 4;

    // ---- Wh slice -> registers (once) ----
    unsigned long long w01[16], w23[16];
#pragma unroll
    for (int kk = 0; kk < 16; ++kk) {
        ulonglong2 v = *reinterpret_cast<const ulonglong2*>(
            Wh + (size_t)(kbase + kk) * HH + jg0);
        w01[kk] = v.x;
        w23[kk] = v.y;
    }

    uint32_t smem_u32;
    asm("{ .reg .u64 t; cvta.to.shared.u64 t, %1; cvt.u32.u64 %0, t; }"
        : "=r"(smem_u32) : "l"(smem));

    // ---- init: mbarriers + h0 (duplicated) into buffer 0 ----
    if (tid == 0) {
#pragma unroll
        for (int r = 0; r < CLUSTER; ++r) {
            MBAR_INIT(smem_u32 + MB_FULL(0, r), 1);
            MBAR_INIT(smem_u32 + MB_FULL(1, r), 1);
            MBAR_EXPECT_TX(smem_u32 + MB_FULL(0, r), CHUNK_TX_BYTES);
            MBAR_EXPECT_TX(smem_u32 + MB_FULL(1, r), CHUNK_TX_BYTES);
        }
        MBAR_INIT(smem_u32 + MB_EMPTY(0), CLUSTER);
        MBAR_INIT(smem_u32 + MB_EMPTY(1), CLUSTER);
    }
    for (int idx = tid; idx < BATCH_PER_CL * HH; idx += 512) {
        float v = h0[(size_t)b0 * HH + idx];
        hdup[idx] = pack_dup(v);
    }
    __syncthreads();
    asm volatile("barrier.cluster.arrive.aligned;\n\t"
                 "barrier.cluster.wait.aligned;" ::: "memory");

    // peer smem base addresses (mapa once)
    uint32_t rbase[CLUSTER];
#pragma unroll
    for (int p = 0; p < CLUSTER; ++p)
        asm("mapa.shared::cluster.u32 %0, %1, %2;"
            : "=r"(rbase[p]) : "r"(smem_u32), "r"(p));

    // output-stage mapping (threads < 256)
    const int fb = (tid >> 6) & 3;
    const int fc = tid & 63;
    const int jg = (int)rank * COLS_PER_CTA + fc;
    float* outp = out + ((size_t)(b0 + fb) * TT) * HH + jg;
    const bool is_red = (tid < 256);

    int pf[2] = {0, 0};   // per-warp parity for full[buf][chunk]
    int pe[2] = {0, 0};   // producer parity for empty[buf]

#pragma unroll 2
    for (int t = 0; t < TT; ++t) {
        const int p = t & 1;
        const int q = p ^ 1;

        // prefetch xwx for this step (independent of h)
        float xw = 0.0f;
        if (is_red) xw = outp[(size_t)t * HH];

        // wait only for MY chunk of h_t (produced by CTA `chunk`)
        if (t > 0) {
            mbar_wait_parity(smem_u32 + MB_FULL(p, chunk), (uint32_t)pf[p]);
            pf[p] ^= 1;
        }

        const unsigned long long* hc = hdup + p * (BATCH_PER_CL * HH);
        unsigned long long a01[4] = {0ULL, 0ULL, 0ULL, 0ULL};
        unsigned long long a23[4] = {0ULL, 0ULL, 0ULL, 0ULL};

#pragma unroll
        for (int kk = 0; kk < 16; ++kk) {
            const int k = kbase + kk;
#pragma unroll
            for (int b = 0; b < 4; ++b) {
                unsigned long long hh = hc[b * HH + k];   // {h,h} pre-duplicated
                ffma2(a01[b], hh, w01[kk]);
                ffma2(a23[b], hh, w23[kk]);
            }
        }

        // partials -> red[kq][b][4cq..4cq+3]
#pragma unroll
        for (int b = 0; b < 4; ++b) {
            ulonglong2 v;
            v.x = a01[b];
            v.y = a23[b];
            *reinterpret_cast<ulonglong2*>(
                &red[(kq * BATCH_PER_CL + b) * COLS_PER_CTA + cq * 4]) = v;
        }
        __syncthreads();   // all partials in red; all reads of hbuf[p] done

        if (tid == 0) {
            if (t > 0) {
                // re-arm full[p][*] for the next fill (stores during t+1)
#pragma unroll
                for (int r = 0; r < CLUSTER; ++r)
                    MBAR_EXPECT_TX(smem_u32 + MB_FULL(p, r), CHUNK_TX_BYTES);
            }
            // signal "this CTA finished reading buffer p" to all 8 CTAs
#pragma unroll
            for (int pp = 0; pp < CLUSTER; ++pp)
                MBAR_ARRIVE_REMOTE(rbase[pp] + MB_EMPTY(p));
        }

        if (is_red) {
            float s0 = xw, s1 = 0.f, s2 = 0.f, s3 = 0.f;
#pragma unroll
            for (int qd = 0; qd < 8; ++qd) {
                s0 += red[((4 * qd + 0) * BATCH_PER_CL + fb) * COLS_PER_CTA + fc];
                s1 += red[((4 * qd + 1) * BATCH_PER_CL + fb) * COLS_PER_CTA + fc];
                s2 += red[((4 * qd + 2) * BATCH_PER_CL + fb) * COLS_PER_CTA + fc];
                s3 += red[((4 * qd + 3) * BATCH_PER_CL + fb) * COLS_PER_CTA + fc];
            }
            float s = (s0 + s1) + (s2 + s3);
            float r;
            asm("tanh.approx.f32 %0, %1;" : "=f"(r) : "f"(s));
            outp[(size_t)t * HH] = r;

            if (t + 1 < TT) {
                // buffer q last read at step t-1; at t==0 it was never read
                // (waiting would deadlock — R5 lesson)
                if (t > 0) {
                    mbar_wait_parity(smem_u32 + MB_EMPTY(q), (uint32_t)pe[q]);
                    pe[q] ^= 1;
                }
                unsigned long long v = pack_dup(r);
                const uint32_t off =
                    (uint32_t)((q * BATCH_PER_CL + fb) * HH + jg) * 8u;
                const uint32_t mboff = (uint32_t)MB_FULL(q, (int)rank);
#pragma unroll
                for (int pp = 0; pp < CLUSTER; ++pp)
                    st_async_b64(rbase[pp] + off, v, rbase[pp] + mboff);
            }
        }
        __syncthreads();   // protect red for next step's partial stores
    }

    // drain before exit
    asm volatile("barrier.cluster.arrive.aligned;\n\t"
                 "barrier.cluster.wait.aligned;" ::: "memory");
}

// ---------------------------------------------------------------------------
// Launch
// ---------------------------------------------------------------------------
extern "C" void kernel_launch(void* const* d_in, const int* in_sizes, int n_in,
                              void* d_out, int out_size) {
    const float* x  = (const float*)d_in[0];
    const float* h0 = (const float*)d_in[1];
    const float* Wx = (const float*)d_in[2];
    const float* Wh = (const float*)d_in[3];
    const float* b  = (const float*)d_in[4];
    float* out = (float*)d_out;

    (void)in_sizes; (void)n_in; (void)out_size;

    dim3 gridA(HH / BN, MM / BM);
    gemm_xwx_kernel<<<gridA, 256>>>(x, Wx, b, out);

    cudaFuncSetAttribute(rnn_cluster_kernel,
                         cudaFuncAttributeMaxDynamicSharedMemorySize,
                         RNN_SMEM_BYTES);
    rnn_cluster_kernel<<<NCTA, 512, RNN_SMEM_BYTES>>>(h0, Wh, out);
}

// round 9
// speedup vs baseline: 1.1469x; 1.1469x over previous
#include <cuda_runtime.h>
#include <cuda_bf16.h>
#include <math.h>
#include <stdint.h>

// Problem constants: N=64, T=512, D=512, H=512, fp32
#define NB   64
#define TT   512
#define DD   512
#define HH   512
#define MM   (NB * TT)

// ---------------------------------------------------------------------------
// f32x2 packed-math helpers
// ---------------------------------------------------------------------------
__device__ __forceinline__ void ffma2(unsigned long long& acc,
                                      unsigned long long a,
                                      unsigned long long b) {
    asm("fma.rn.f32x2 %0, %1, %2, %0;" : "+l"(acc) : "l"(a), "l"(b));
}
__device__ __forceinline__ unsigned long long add2(unsigned long long a,
                                                   unsigned long long b) {
    unsigned long long r;
    asm("add.rn.f32x2 %0, %1, %2;" : "=l"(r) : "l"(a), "l"(b));
    return r;
}
__device__ __forceinline__ unsigned long long pack_dup(float v) {
    unsigned long long r;
    unsigned u = __float_as_uint(v);
    asm("mov.b64 %0, {%1, %1};" : "=l"(r) : "r"(u));
    return r;
}
__device__ __forceinline__ unsigned long long pack2(float lo, float hi) {
    unsigned long long r;
    asm("mov.b64 %0, {%1, %2};" : "=l"(r) : "f"(lo), "f"(hi));
    return r;
}

// mbarrier helpers -----------------------------------------------------------
#define MBAR_INIT(addr, cnt) \
    asm volatile("mbarrier.init.shared.b64 [%0], %1;" :: "r"(addr), "r"(cnt) : "memory")
#define MBAR_EXPECT_TX(addr, bytes) \
    asm volatile("mbarrier.arrive.expect_tx.shared.b64 _, [%0], %1;" \
                 :: "r"(addr), "r"(bytes) : "memory")
#define MBAR_ARRIVE_REMOTE(addr) \
    asm volatile("mbarrier.arrive.shared::cluster.b64 _, [%0];" :: "r"(addr) : "memory")

__device__ __forceinline__ void mbar_wait_parity(uint32_t mbar, uint32_t parity) {
    asm volatile(
        "{\n\t"
        ".reg .pred P;\n\t"
        "WL_%=:\n\t"
        "mbarrier.try_wait.parity.acquire.cluster.shared::cta.b64 P, [%0], %1, 0x989680;\n\t"
        "@P bra WD_%=;\n\t"
        "bra WL_%=;\n\t"
        "WD_%=:\n\t"
        "}" :: "r"(mbar), "r"(parity) : "memory");
}

__device__ __forceinline__ void st_async_b64(uint32_t raddr, unsigned long long v,
                                             uint32_t rmbar) {
    asm volatile(
        "st.async.shared::cluster.mbarrier::complete_tx::bytes.b64 [%0], %1, [%2];"
        :: "r"(raddr), "l"(v), "r"(rmbar) : "memory");
}

// ---------------------------------------------------------------------------
// Kernel A: xwx = x @ Wx + b  (into d_out), FFMA2 SGEMM (unchanged)
// ---------------------------------------------------------------------------
#define BM 128
#define BN 128
#define BK 8

__global__ __launch_bounds__(256) void gemm_xwx_kernel(
    const float* __restrict__ X,
    const float* __restrict__ Wx,
    const float* __restrict__ bias,
    float* __restrict__ out)
{
    __shared__ float2 Asd[BK][BM];
    __shared__ float  Bs[BK][BN];

    const int tid = threadIdx.x;
    const int m0 = blockIdx.y * BM;
    const int n0 = blockIdx.x * BN;

    const int arow = tid >> 1;
    const int acol = (tid & 1) * 4;
    const int brow = tid >> 5;
    const int bcol = (tid & 31) * 4;

    const int ty = tid >> 4;
    const int tx = tid & 15;

    unsigned long long acc2[8][4];
#pragma unroll
    for (int i = 0; i < 8; ++i)
#pragma unroll
        for (int j = 0; j < 4; ++j) acc2[i][j] = 0ULL;

    for (int k0 = 0; k0 < DD; k0 += BK) {
        float4 av = *reinterpret_cast<const float4*>(
            X + (size_t)(m0 + arow) * DD + k0 + acol);
        float4 bv = *reinterpret_cast<const float4*>(
            Wx + (size_t)(k0 + brow) * HH + n0 + bcol);

        Asd[acol + 0][arow] = make_float2(av.x, av.x);
        Asd[acol + 1][arow] = make_float2(av.y, av.y);
        Asd[acol + 2][arow] = make_float2(av.z, av.z);
        Asd[acol + 3][arow] = make_float2(av.w, av.w);
        *reinterpret_cast<float4*>(&Bs[brow][bcol]) = bv;
        __syncthreads();

#pragma unroll
        for (int k = 0; k < BK; ++k) {
            unsigned long long a2[8], b2[4];
            ulonglong2 t0 = *reinterpret_cast<const ulonglong2*>(&Bs[k][tx * 8]);
            ulonglong2 t1 = *reinterpret_cast<const ulonglong2*>(&Bs[k][tx * 8 + 4]);
            b2[0] = t0.x; b2[1] = t0.y; b2[2] = t1.x; b2[3] = t1.y;
#pragma unroll
            for (int i = 0; i < 8; ++i)
                a2[i] = *reinterpret_cast<const unsigned long long*>(&Asd[k][ty * 8 + i]);
#pragma unroll
            for (int i = 0; i < 8; ++i)
#pragma unroll
                for (int j = 0; j < 4; ++j)
                    ffma2(acc2[i][j], a2[i], b2[j]);
        }
        __syncthreads();
    }

    unsigned long long bb2[4];
    {
        ulonglong2 t0 = *reinterpret_cast<const ulonglong2*>(bias + n0 + tx * 8);
        ulonglong2 t1 = *reinterpret_cast<const ulonglong2*>(bias + n0 + tx * 8 + 4);
        bb2[0] = t0.x; bb2[1] = t0.y; bb2[2] = t1.x; bb2[3] = t1.y;
    }
#pragma unroll
    for (int i = 0; i < 8; ++i) {
        float* orow = out + (size_t)(m0 + ty * 8 + i) * HH + n0 + tx * 8;
        ulonglong2 v0, v1;
        v0.x = add2(acc2[i][0], bb2[0]);
        v0.y = add2(acc2[i][1], bb2[1]);
        v1.x = add2(acc2[i][2], bb2[2]);
        v1.y = add2(acc2[i][3], bb2[3]);
        *reinterpret_cast<ulonglong2*>(orow)     = v0;
        *reinterpret_cast<ulonglong2*>(orow + 4) = v1;
    }
}

// ---------------------------------------------------------------------------
// Kernel B: cluster recurrence. R6 dataflow (8 KB/step b64 col-pair exchange,
// float4-h + pack_dup k-loop) + R7 chunked full barriers:
//   full[buf][r] (r = source rank) expect_tx = 1024 B. Consumer warp waits
//   only for its own chunk (k in [64r,64r+64) <=> warp pair tid>>6 == r), so
//   inter-CTA skew pipelines through chunks instead of global-maxing.
// Housekeeping parallelized: thread r does {expect_tx full[p][r]; remote
// arrive empty[p] -> CTA r} — per-thread order gives exactly the required
// protocol ordering (CTA r's next store to my full[p][r] is gated by my
// arrive reaching CTA r, which follows my re-arm).
// ---------------------------------------------------------------------------
#define CLUSTER       8
#define NCTA          128
#define BATCH_PER_CL  4
#define COLS_PER_CTA  64

#define HBUF_ELEMS (2 * BATCH_PER_CL * HH)             // 4096 floats (16 KB)
#define RED_ELEMS  (32 * BATCH_PER_CL * COLS_PER_CTA)  // 8192 floats (32 KB)
#define MBAR_OFF   ((HBUF_ELEMS + RED_ELEMS) * 4)      // 49152 bytes
// mbar layout: full[2][8] at +0..128 (stride 8), empty[2] at +128, +136
#define MB_FULL(p, r) (MBAR_OFF + ((p) * 8 + (r)) * 8)
#define MB_EMPTY(p)   (MBAR_OFF + 128 + (p) * 8)
#define RNN_SMEM_BYTES (MBAR_OFF + 160)

#define CHUNK_TX_BYTES 1024   // 128 producer threads x 8 B land per peer chunk

__global__ __launch_bounds__(512, 1) __cluster_dims__(CLUSTER, 1, 1)
void rnn_cluster_kernel(const float* __restrict__ h0,
                        const float* __restrict__ Wh,
                        float* __restrict__ out)
{
    extern __shared__ float smem[];
    float* hbuf = smem;                 // [2][4][HH]
    float* red  = smem + HBUF_ELEMS;    // [32][4][64]

    const int tid = threadIdx.x;
    uint32_t rank;
    asm("mov.u32 %0, %%cluster_ctarank;" : "=r"(rank));
    const int cid = blockIdx.x >> 3;
    const int b0  = cid * BATCH_PER_CL;

    const int kq    = tid >> 4;          // 0..31
    const int cq    = tid & 15;          // 0..15
    const int kbase = kq * 16;
    const int chunk = tid >> 6;          // 0..7: source rank my warp consumes
    const int jg0   = (int)rank * COLS_PER_CTA + cq * 4;

    // ---- Wh slice -> registers (once) ----
    unsigned long long w01[16], w23[16];
#pragma unroll
    for (int kk = 0; kk < 16; ++kk) {
        ulonglong2 v = *reinterpret_cast<const ulonglong2*>(
            Wh + (size_t)(kbase + kk) * HH + jg0);
        w01[kk] = v.x;
        w23[kk] = v.y;
    }

    uint32_t smem_u32;
    asm("{ .reg .u64 t; cvta.to.shared.u64 t, %1; cvt.u32.u64 %0, t; }"
        : "=r"(smem_u32) : "l"(smem));

    // ---- init: mbarriers + h0 into buffer 0 ----
    if (tid == 0) {
#pragma unroll
        for (int r = 0; r < CLUSTER; ++r) {
            MBAR_INIT(smem_u32 + MB_FULL(0, r), 1);
            MBAR_INIT(smem_u32 + MB_FULL(1, r), 1);
            MBAR_EXPECT_TX(smem_u32 + MB_FULL(0, r), CHUNK_TX_BYTES);
            MBAR_EXPECT_TX(smem_u32 + MB_FULL(1, r), CHUNK_TX_BYTES);
        }
        MBAR_INIT(smem_u32 + MB_EMPTY(0), CLUSTER);
        MBAR_INIT(smem_u32 + MB_EMPTY(1), CLUSTER);
    }
    for (int idx = tid; idx < BATCH_PER_CL * HH; idx += 512)
        hbuf[idx] = h0[(size_t)b0 * HH + idx];
    __syncthreads();
    asm volatile("barrier.cluster.arrive.aligned;\n\t"
                 "barrier.cluster.wait.aligned;" ::: "memory");

    // peer smem base addresses (mapa once)
    uint32_t rbase[CLUSTER];
#pragma unroll
    for (int p = 0; p < CLUSTER; ++p)
        asm("mapa.shared::cluster.u32 %0, %1, %2;"
            : "=r"(rbase[p]) : "r"(smem_u32), "r"(p));

    // output-stage mapping (threads < 256)
    const int fb = (tid >> 6) & 3;
    const int fc = tid & 63;
    const int jg = (int)rank * COLS_PER_CTA + fc;
    float* outp = out + ((size_t)(b0 + fb) * TT) * HH + jg;
    const bool is_red   = (tid < 256);
    const bool is_store = (tid < 256) && ((tid & 1) == 0);
    const bool is_hk    = (tid < CLUSTER);   // housekeeping thread (one per rank)

    int pf[2] = {0, 0};   // per-warp parity for full[buf][chunk]
    int pe[2] = {0, 0};   // producer parity for empty[buf]

#pragma unroll 2
    for (int t = 0; t < TT; ++t) {
        const int p = t & 1;
        const int q = p ^ 1;

        // prefetch xwx for this step (independent of h)
        float xw = 0.0f;
        if (is_red) xw = outp[(size_t)t * HH];

        // wait only for MY chunk of h_t (produced by CTA `chunk`)
        if (t > 0) {
            mbar_wait_parity(smem_u32 + MB_FULL(p, chunk), (uint32_t)pf[p]);
            pf[p] ^= 1;
        }

        const float* hc = hbuf + p * (BATCH_PER_CL * HH);
        unsigned long long a01[4] = {0ULL, 0ULL, 0ULL, 0ULL};
        unsigned long long a23[4] = {0ULL, 0ULL, 0ULL, 0ULL};

#pragma unroll
        for (int kk4 = 0; kk4 < 4; ++kk4) {
            const int k = kbase + kk4 * 4;
#pragma unroll
            for (int b = 0; b < 4; ++b) {
                float4 hv = *reinterpret_cast<const float4*>(&hc[b * HH + k]);
                unsigned long long hh;
                hh = pack_dup(hv.x);
                ffma2(a01[b], hh, w01[kk4 * 4 + 0]);
                ffma2(a23[b], hh, w23[kk4 * 4 + 0]);
                hh = pack_dup(hv.y);
                ffma2(a01[b], hh, w01[kk4 * 4 + 1]);
                ffma2(a23[b], hh, w23[kk4 * 4 + 1]);
                hh = pack_dup(hv.z);
                ffma2(a01[b], hh, w01[kk4 * 4 + 2]);
                ffma2(a23[b], hh, w23[kk4 * 4 + 2]);
                hh = pack_dup(hv.w);
                ffma2(a01[b], hh, w01[kk4 * 4 + 3]);
                ffma2(a23[b], hh, w23[kk4 * 4 + 3]);
            }
        }

        // partials -> red[kq][b][4cq..4cq+3]
#pragma unroll
        for (int b = 0; b < 4; ++b) {
            ulonglong2 v;
            v.x = a01[b];
            v.y = a23[b];
            *reinterpret_cast<ulonglong2*>(
                &red[(kq * BATCH_PER_CL + b) * COLS_PER_CTA + cq * 4]) = v;
        }
        __syncthreads();   // all partials in red; all reads of hbuf[p] done

        // Housekeeping (parallel, thread r = 0..7):
        //   1) re-arm my full[p][r] for its next fill (skipped at t==0,
        //      pre-armed at init)
        //   2) credit CTA r: arrive on its empty[p]
        // Per-thread order (1)->(2) is exactly the required protocol order.
        if (is_hk) {
            if (t > 0)
                MBAR_EXPECT_TX(smem_u32 + MB_FULL(p, tid), CHUNK_TX_BYTES);
            MBAR_ARRIVE_REMOTE(rbase[tid] + MB_EMPTY(p));
        }

        if (is_red) {
            float s0 = xw, s1 = 0.f, s2 = 0.f, s3 = 0.f;
#pragma unroll
            for (int qd = 0; qd < 8; ++qd) {
                s0 += red[((4 * qd + 0) * BATCH_PER_CL + fb) * COLS_PER_CTA + fc];
                s1 += red[((4 * qd + 1) * BATCH_PER_CL + fb) * COLS_PER_CTA + fc];
                s2 += red[((4 * qd + 2) * BATCH_PER_CL + fb) * COLS_PER_CTA + fc];
                s3 += red[((4 * qd + 3) * BATCH_PER_CL + fb) * COLS_PER_CTA + fc];
            }
            float s = (s0 + s1) + (s2 + s3);
            float r;
            asm("tanh.approx.f32 %0, %1;" : "=f"(r) : "f"(s));
            outp[(size_t)t * HH] = r;

            if (t + 1 < TT) {
                // pair adjacent columns for 8-byte remote stores
                float rn = __shfl_down_sync(0xFFFFFFFFu, r, 1);
                if (is_store) {
                    unsigned long long v = pack2(r, rn);
                    // buffer q last read at t-1; at t==0 it was never read
                    // (waiting would deadlock — R5 lesson)
                    if (t > 0) {
                        mbar_wait_parity(smem_u32 + MB_EMPTY(q), (uint32_t)pe[q]);
                        pe[q] ^= 1;
                    }
                    const uint32_t off =
                        (uint32_t)((q * BATCH_PER_CL + fb) * HH + jg) * 4u;
                    const uint32_t mboff = (uint32_t)MB_FULL(q, (int)rank);
#pragma unroll
                    for (int pp = 0; pp < CLUSTER; ++pp)
                        st_async_b64(rbase[pp] + off, v, rbase[pp] + mboff);
                }
            }
        }
        __syncthreads();   // protect red for next step's partial stores
    }

    // drain before exit
    asm volatile("barrier.cluster.arrive.aligned;\n\t"
                 "barrier.cluster.wait.aligned;" ::: "memory");
}

// ---------------------------------------------------------------------------
// Launch
// ---------------------------------------------------------------------------
extern "C" void kernel_launch(void* const* d_in, const int* in_sizes, int n_in,
                              void* d_out, int out_size) {
    const float* x  = (const float*)d_in[0];
    const float* h0 = (const float*)d_in[1];
    const float* Wx = (const float*)d_in[2];
    const float* Wh = (const float*)d_in[3];
    const float* b  = (const float*)d_in[4];
    float* out = (float*)d_out;

    (void)in_sizes; (void)n_in; (void)out_size;

    dim3 gridA(HH / BN, MM / BM);
    gemm_xwx_kernel<<<gridA, 256>>>(x, Wx, b, out);

    cudaFuncSetAttribute(rnn_cluster_kernel,
                         cudaFuncAttributeMaxDynamicSharedMemorySize,
                         RNN_SMEM_BYTES);
    rnn_cluster_kernel<<<NCTA, 512, RNN_SMEM_BYTES>>>(h0, Wh, out);
}